// round 16
// baseline (speedup 1.0000x reference)
#include <cuda_runtime.h>
#include <cstdint>

#define Bsz 8
#define Nn 2048
#define FIN 128
#define FO 64
#define ALPHA 0.2f

#define BM 32
#define BN 32
#define NZ 4                       // j-split factor
#define NTILES (Nn / BN / NZ)      // 16 tiles per CTA
#define NS 3                       // cp.async pipeline stages
#define PPITCH 258                 // sP group pitch (words): ≡2 mod 8 → CF LDS.64

// Scratch device globals (allocation-free per harness rules)
__device__ float g_WhT[Bsz * FO * Nn];       // transposed: [b][o][n]
__device__ float g_e1[Bsz * Nn];
__device__ float g_e2[Bsz * Nn];
__device__ float g_pN[NZ][Bsz * Nn * FO];    // partial numerators (4 MB each)
__device__ float g_pS[NZ][Bsz * Nn];         // partial row sums

// ---------------------------------------------------------------------------
// helpers
// ---------------------------------------------------------------------------
static __device__ __forceinline__ uint32_t smem_u32(const void* p) {
    uint32_t a;
    asm("{ .reg .u64 t; cvta.to.shared.u64 t, %1; cvt.u32.u64 %0, t; }"
        : "=r"(a) : "l"(p));
    return a;
}
static __device__ __forceinline__ void cp16(uint32_t dst, const void* src) {
    asm volatile("cp.async.cg.shared.global [%0], [%1], 16;"
                 :: "r"(dst), "l"(src) : "memory");
}
#define CP_COMMIT() asm volatile("cp.async.commit_group;" ::: "memory")
#define CP_WAIT1()  asm volatile("cp.async.wait_group 1;" ::: "memory")

static __device__ __forceinline__ float tf32r(float x) {
    uint32_t u;
    asm("cvt.rna.tf32.f32 %0, %1;" : "=r"(u) : "f"(x));
    return __uint_as_float(u);
}

static __device__ __forceinline__ void mma_tf32(
    float* d, uint32_t a0, uint32_t a1, uint32_t a2, uint32_t a3,
    uint32_t b0, uint32_t b1)
{
    asm volatile(
        "mma.sync.aligned.m16n8k8.row.col.f32.tf32.tf32.f32 "
        "{%0,%1,%2,%3},{%4,%5,%6,%7},{%8,%9},{%0,%1,%2,%3};"
        : "+f"(d[0]), "+f"(d[1]), "+f"(d[2]), "+f"(d[3])
        : "r"(a0), "r"(a1), "r"(a2), "r"(a3), "r"(b0), "r"(b1));
}

// ---------------------------------------------------------------------------
// Kernel 1: Wh = h @ W (written TRANSPOSED as WhT[b][o][n]); e1 = Wh·a1; e2 = Wh·a2
// ---------------------------------------------------------------------------
__global__ __launch_bounds__(256) void gat_proj_kernel(
    const float* __restrict__ h,
    const float* __restrict__ W,
    const float* __restrict__ a)
{
    __shared__ float sW[FIN * FO];   // 32 KB
    __shared__ float sT[FO * 33];    // transpose staging, pitch 33

    const int t = threadIdx.x;
#pragma unroll
    for (int r = 0; r < 8; r++)
        *(float4*)&sW[r * 1024 + t * 4] = *(const float4*)&W[r * 1024 + t * 4];

    const int warp = t >> 5;
    const int lane = t & 31;
    const int g0 = blockIdx.x * 32;
    const int i0 = g0 + warp * 4;

    const float a1l = a[lane];
    const float a1h = a[lane + 32];
    const float a2l = a[FO + lane];
    const float a2h = a[FO + 32 + lane];

    __syncthreads();

    float hr[4][4];
#pragma unroll
    for (int r = 0; r < 4; r++) {
        const float* hp = h + (long)(i0 + r) * FIN;
#pragma unroll
        for (int q = 0; q < 4; q++) hr[r][q] = hp[q * 32 + lane];
    }

    float acc[4][2];
#pragma unroll
    for (int r = 0; r < 4; r++) { acc[r][0] = 0.f; acc[r][1] = 0.f; }

#pragma unroll
    for (int q = 0; q < 4; q++) {
#pragma unroll
        for (int kk = 0; kk < 32; kk++) {
            const int k = q * 32 + kk;
            const float w0 = sW[k * FO + lane];
            const float w1 = sW[k * FO + 32 + lane];
#pragma unroll
            for (int r = 0; r < 4; r++) {
                const float hv = __shfl_sync(0xffffffffu, hr[r][q], kk);
                acc[r][0] = fmaf(hv, w0, acc[r][0]);
                acc[r][1] = fmaf(hv, w1, acc[r][1]);
            }
        }
    }

#pragma unroll
    for (int r = 0; r < 4; r++) {
        sT[lane * 33 + warp * 4 + r]        = acc[r][0];
        sT[(lane + 32) * 33 + warp * 4 + r] = acc[r][1];
    }

#pragma unroll
    for (int r = 0; r < 4; r++) {
        float e1 = acc[r][0] * a1l + acc[r][1] * a1h;
        float e2 = acc[r][0] * a2l + acc[r][1] * a2h;
#pragma unroll
        for (int off = 16; off > 0; off >>= 1) {
            e1 += __shfl_xor_sync(0xffffffffu, e1, off);
            e2 += __shfl_xor_sync(0xffffffffu, e2, off);
        }
        if (lane == 0) {
            g_e1[i0 + r] = e1;
            g_e2[i0 + r] = e2;
        }
    }

    __syncthreads();

    const int bb = g0 >> 11;
    const int il = g0 & (Nn - 1);
    const int oB = t >> 3;
    const int ii = (t & 7) * 4;
#pragma unroll
    for (int hf = 0; hf < 2; hf++) {
        const int o = hf * 32 + oB;
        float4 v;
        v.x = sT[o * 33 + ii + 0];
        v.y = sT[o * 33 + ii + 1];
        v.z = sT[o * 33 + ii + 2];
        v.w = sT[o * 33 + ii + 3];
        *(float4*)&g_WhT[((long)(bb * FO + o)) * Nn + il + ii] = v;
    }
}

// ---------------------------------------------------------------------------
// Kernel 2: PARTIAL masked-softmax aggregation via mma.sync tf32.
// grid (64, 8, 4) = 2048 CTAs, 256 threads. Each z-quarter handles 512 j's
// (16 tiles). Writes unnormalized numerators + partial row sums.
// ---------------------------------------------------------------------------
__global__ __launch_bounds__(256, 4) void gat_agg_partial_kernel(
    const int* __restrict__ adj)
{
    __shared__ __align__(16) int   sAdj[NS][BM * BN];   // 12 KB
    __shared__ __align__(16) float sVT[NS][FO * BN];    // 24 KB (XOR-swizzled)
    __shared__ __align__(16) float sP[2][4 * PPITCH];   // ~8.1 KB (grouped by c&3)

    const int b  = blockIdx.y;
    const int i0 = blockIdx.x * BM;
    const int zh = blockIdx.z;          // j-quarter
    const int jz = zh * (Nn / NZ);      // j base offset
    const int t  = threadIdx.x;
    const int warp = t >> 5;
    const int lane = t & 31;

    // score mapping: thread <-> (row, 4 j's)
    const int rowi = t >> 3;            // 0..31
    const int jq   = (t & 7) * 4;       // 0..28
    const int qP   = jq >> 2;           // 0..7 (q index into grouped sP)
    const float e1i = g_e1[b * Nn + i0 + rowi];
    const int*   adjRow = adj + ((long)(b * Nn + i0 + rowi)) * Nn + jz + jq;
    const float* e2p    = g_e2 + b * Nn + jz + jq;

    // V staging: thread <-> (o, 8 j's)
    const int vo = t >> 2;              // 0..63
    const int vq = (t & 3) * 8;         // 0..24
    const int vsw = (vo & 7) << 2;
    const float* vsrc = g_WhT + ((long)(b * FO + vo)) * Nn + jz + vq;

    // per-thread fixed smem dst addresses
    const uint32_t adjDst = smem_u32(&sAdj[0][0]) + (uint32_t)((rowi * BN + jq) * 4);
    const uint32_t vDst0  = smem_u32(&sVT[0][0]) + (uint32_t)(((vo << 5) + (vq ^ vsw)) * 4);
    const uint32_t vDst1  = smem_u32(&sVT[0][0]) + (uint32_t)(((vo << 5) + ((vq + 4) ^ vsw)) * 4);

    // matmul mapping: warp tile 16 rows x 16 cols
    const int wm = warp & 1;
    const int wn = warp >> 1;           // 0..3
    const int lq = lane >> 2;
    const int lr = lane & 3;
    const int r0 = wm * 16 + lq;
    const int r1 = r0 + 8;
    const int aOff0 = lr * PPITCH + r0 * 8;
    const int aOff1 = lr * PPITCH + r1 * 8;

    float acc[2][4];
#pragma unroll
    for (int n = 0; n < 2; n++)
#pragma unroll
        for (int r = 0; r < 4; r++) acc[n][r] = 0.f;

    float ssum = 0.f;

    // ---- prologue: issue stages for tiles 0, 1 ----
#pragma unroll
    for (int s = 0; s < NS - 1; s++) {
        cp16(adjDst + (uint32_t)(s * BM * BN * 4), adjRow + s * BN);
        cp16(vDst0 + (uint32_t)(s * FO * BN * 4), vsrc + s * BN);
        cp16(vDst1 + (uint32_t)(s * FO * BN * 4), vsrc + s * BN + 4);
        CP_COMMIT();
    }
    float4 e2cur = *(const float4*)(e2p);

    int stg = 0;        // stage of current tile
    int stgI = NS - 1;  // stage being filled this iteration (tile t+NS-1)

    for (int tile = 0; tile < NTILES; tile++) {
        const int buf = tile & 1;

        // prefetch next tile's e2 into registers (L2-resident, tiny)
        float4 e2nxt;
        if (tile < NTILES - 1) e2nxt = *(const float4*)(e2p + (tile + 1) * BN);

        CP_WAIT1();   // tile's stage (own adj words + own V words) done

        // ---- scores from own adj words; store into grouped sP layout ----
        {
            const int4 av = *(const int4*)&sAdj[stg][rowi * BN + jq];
            float p0, p1, p2, p3;
            float x;
            x = e1i + e2cur.x; x = fmaxf(x, ALPHA * x);
            p0 = (av.x > 0) ? tf32r(__expf(x)) : 0.f;
            x = e1i + e2cur.y; x = fmaxf(x, ALPHA * x);
            p1 = (av.y > 0) ? tf32r(__expf(x)) : 0.f;
            x = e1i + e2cur.z; x = fmaxf(x, ALPHA * x);
            p2 = (av.z > 0) ? tf32r(__expf(x)) : 0.f;
            x = e1i + e2cur.w; x = fmaxf(x, ALPHA * x);
            p3 = (av.w > 0) ? tf32r(__expf(x)) : 0.f;
            ssum += (p0 + p1) + (p2 + p3);
            float* pb = &sP[buf][rowi * 8 + qP];
            pb[0 * PPITCH] = p0;
            pb[1 * PPITCH] = p1;
            pb[2 * PPITCH] = p2;
            pb[3 * PPITCH] = p3;
        }
        e2cur = e2nxt;

        __syncthreads();   // sP/sVT visible to all; MMA(tile-1) fully done

        // ---- issue loads for tile+NS-1 (overwrites stage (tile-1)%NS, now safe) ----
        {
            const int jt = tile + NS - 1;
            if (jt < NTILES) {
                const uint32_t so  = (uint32_t)(stgI * BM * BN * 4);
                const uint32_t vso = (uint32_t)(stgI * FO * BN * 4);
                cp16(adjDst + so, adjRow + jt * BN);
                cp16(vDst0 + vso, vsrc + jt * BN);
                cp16(vDst1 + vso, vsrc + jt * BN + 4);
            }
            CP_COMMIT();   // commit even if empty: keeps group count uniform
        }

        // ---- MMA: 4 k-steps x 2 n-tiles, m16n8k8 tf32 ----
        const float* cP = &sP[buf][0];
        const float* cV = &sVT[stg][0];
#pragma unroll
        for (int k = 0; k < 4; k++) {
            const float2 a02 = *(const float2*)&cP[aOff0 + 2 * k];  // (a0, a2)
            const float2 a13 = *(const float2*)&cP[aOff1 + 2 * k];  // (a1, a3)
#pragma unroll
            for (int nt = 0; nt < 2; nt++) {
                const int o = wn * 16 + nt * 8 + lq;
                const int s = (o & 7) << 2;
                const int jb = k * 8 + lr;
                const uint32_t b0 = __float_as_uint(cV[(o << 5) + (jb ^ s)]);
                const uint32_t b1 = __float_as_uint(cV[(o << 5) + ((jb + 4) ^ s)]);
                mma_tf32(acc[nt],
                         __float_as_uint(a02.x), __float_as_uint(a13.x),
                         __float_as_uint(a02.y), __float_as_uint(a13.y),
                         b0, b1);
            }
        }

        stg  = (stg == NS - 1) ? 0 : stg + 1;
        stgI = (stgI == NS - 1) ? 0 : stgI + 1;
    }

    // ---- partial row sums: reduce over 8 threads sharing a row, write gmem ----
    ssum += __shfl_xor_sync(0xffffffffu, ssum, 1);
    ssum += __shfl_xor_sync(0xffffffffu, ssum, 2);
    ssum += __shfl_xor_sync(0xffffffffu, ssum, 4);
    if ((t & 7) == 0) g_pS[zh][b * Nn + i0 + rowi] = ssum;

    // ---- epilogue: store raw partial numerators (no normalize) ----
    {
        float* o0 = &g_pN[zh][((long)(b * Nn + i0 + r0)) * FO];
        float* o1 = &g_pN[zh][((long)(b * Nn + i0 + r1)) * FO];
#pragma unroll
        for (int nt = 0; nt < 2; nt++) {
            const int col = wn * 16 + nt * 8 + lr * 2;
            *(float2*)(o0 + col) = make_float2(acc[nt][0], acc[nt][1]);
            *(float2*)(o1 + col) = make_float2(acc[nt][2], acc[nt][3]);
        }
    }
}

// ---------------------------------------------------------------------------
// Kernel 3: combine quarters, normalize, ELU.
// 16384 rows x 64 cols; 1 thread per 4 cols -> 262144 threads, 1024 blocks.
// ---------------------------------------------------------------------------
__global__ __launch_bounds__(256) void gat_combine_kernel(float* __restrict__ out)
{
    const int idx = blockIdx.x * 256 + threadIdx.x;
    const int row = idx >> 4;
    const int cq  = (idx & 15) * 4;

    float s = 0.f;
#pragma unroll
    for (int z = 0; z < NZ; z++) s += g_pS[z][row];
    const float inv = 1.0f / s;

    float4 n = *(const float4*)&g_pN[0][(long)row * FO + cq];
#pragma unroll
    for (int z = 1; z < NZ; z++) {
        const float4 nz = *(const float4*)&g_pN[z][(long)row * FO + cq];
        n.x += nz.x; n.y += nz.y; n.z += nz.z; n.w += nz.w;
    }

    float4 o;
    float x;
    x = n.x * inv; o.x = (x > 0.f) ? x : expm1f(x);
    x = n.y * inv; o.y = (x > 0.f) ? x : expm1f(x);
    x = n.z * inv; o.z = (x > 0.f) ? x : expm1f(x);
    x = n.w * inv; o.w = (x > 0.f) ? x : expm1f(x);
    *(float4*)&out[(long)row * FO + cq] = o;
}

// ---------------------------------------------------------------------------
extern "C" void kernel_launch(void* const* d_in, const int* in_sizes, int n_in,
                              void* d_out, int out_size)
{
    const float* h   = (const float*)d_in[0];
    const int*   adj = (const int*)d_in[1];
    const float* W   = (const float*)d_in[2];
    const float* a   = (const float*)d_in[3];
    float* out = (float*)d_out;

    gat_proj_kernel<<<(Bsz * Nn) / 32, 256>>>(h, W, a);
    gat_agg_partial_kernel<<<dim3(Nn / BM, Bsz, NZ), 256>>>(adj);
    gat_combine_kernel<<<(Bsz * Nn * FO / 4) / 256, 256>>>(out);
}